// round 6
// baseline (speedup 1.0000x reference)
#include <cuda_runtime.h>
#include <cuda_fp16.h>
#include <cstdint>

#define N_USERS 30000
#define N_ENT   70000
#define N_NODES 100000
#define N_EDGES 1600000

#define SCAN_BS 512
#define SCAN_NB ((N_NODES + SCAN_BS - 1) / SCAN_BS)   // 196

typedef unsigned long long ull;

// Scratch
__device__ float4  g_egoA[N_NODES * 16];     // layer-0 ego fp32
__device__ float2  g_egoB[N_NODES * 32];     // layer-1 ego fp32
__device__ __half2 g_egoAh[N_NODES * 32];    // fp16 shadows (gather only)
__device__ __half2 g_egoBh[N_NODES * 32];
__device__ int  g_cnt[N_NODES];
__device__ int  g_off[N_NODES + 1];
__device__ int  g_cur[N_NODES];
__device__ ull  g_state[SCAN_NB];            // lookback: (status<<32)|value
__device__ int2 g_edges[N_EDGES];            // row-sorted (col, val bits)

// ---- f32x2 packed helpers -------------------------------------------------
__device__ __forceinline__ ull pack2(float a, float b) {
    ull r; asm("mov.b64 %0, {%1, %2};" : "=l"(r) : "f"(a), "f"(b)); return r;
}
__device__ __forceinline__ void unpack2(ull p, float& a, float& b) {
    asm("mov.b64 {%0, %1}, %2;" : "=f"(a), "=f"(b) : "l"(p));
}
__device__ __forceinline__ void fma2(ull& d, ull a, ull b) {
    asm("fma.rn.f32x2 %0, %1, %2, %0;" : "+l"(d) : "l"(a), "l"(b));
}

// ---------------------------------------------------------------------------
// k_init: ego0 (fp32 + fp16 shadow), out[:,0:64], edge histogram.
// g_cnt and g_state zeroed beforehand via cudaMemsetAsync.
// ---------------------------------------------------------------------------
__global__ __launch_bounds__(256) void k_init(
    const float4* __restrict__ user4,
    const float4* __restrict__ ent4,
    const int* __restrict__ rows,
    float4* __restrict__ out4)
{
    int idx = blockIdx.x * blockDim.x + threadIdx.x;
    if (idx < N_EDGES) atomicAdd(&g_cnt[rows[idx]], 1);
    if (idx >= N_NODES * 16) return;
    int row = idx >> 4;
    int part = idx & 15;
    float4 v = (row < N_USERS) ? user4[row * 16 + part]
                               : ent4[(row - N_USERS) * 16 + part];
    g_egoA[idx] = v;
    g_egoAh[row * 32 + 2 * part]     = __floats2half2_rn(v.x, v.y);
    g_egoAh[row * 32 + 2 * part + 1] = __floats2half2_rn(v.z, v.w);
    out4[row * 40 + part] = v;
}

// ---------------------------------------------------------------------------
// Single-pass exclusive scan of g_cnt (decoupled lookback), writes g_off/g_cur.
// ---------------------------------------------------------------------------
__global__ __launch_bounds__(SCAN_BS) void k_scan()
{
    __shared__ int warp_sums[16];
    __shared__ int blk_prefix;

    int tid = threadIdx.x;
    int bid = blockIdx.x;
    int lane = tid & 31;
    int wid = tid >> 5;
    int i = bid * SCAN_BS + tid;
    int v = (i < N_NODES) ? g_cnt[i] : 0;

    // warp inclusive scan
    int x = v;
    #pragma unroll
    for (int off = 1; off < 32; off <<= 1) {
        int t = __shfl_up_sync(0xFFFFFFFFu, x, off);
        if (lane >= off) x += t;
    }
    if (lane == 31) warp_sums[wid] = x;
    __syncthreads();
    if (wid == 0) {
        int s = (lane < 16) ? warp_sums[lane] : 0;
        #pragma unroll
        for (int off = 1; off < 16; off <<= 1) {
            int t = __shfl_up_sync(0xFFFFFFFFu, s, off);
            if (lane >= off) s += t;
        }
        if (lane < 16) warp_sums[lane] = s;
    }
    __syncthreads();
    int incl = x + (wid > 0 ? warp_sums[wid - 1] : 0);
    int block_total = warp_sums[15];

    if (tid == 0) {
        if (bid == 0) {
            atomicExch(&g_state[0], (2ULL << 32) | (unsigned)block_total);
            blk_prefix = 0;
        } else {
            atomicExch(&g_state[bid], (1ULL << 32) | (unsigned)block_total);
            int pref = 0;
            int j = bid - 1;
            while (true) {
                ull s = atomicAdd(&g_state[j], 0ULL);   // atomic read
                unsigned st = (unsigned)(s >> 32);
                if (st == 2) { pref += (int)(unsigned)s; break; }
                if (st == 1) { pref += (int)(unsigned)s; j--; }
            }
            atomicExch(&g_state[bid], (2ULL << 32) | (unsigned)(pref + block_total));
            blk_prefix = pref;
        }
    }
    __syncthreads();

    int excl = blk_prefix + incl - v;
    if (i < N_NODES) { g_off[i] = excl; g_cur[i] = excl; }
    if (i == N_NODES - 1) g_off[N_NODES] = N_EDGES;
}

__global__ __launch_bounds__(256) void k_scatter(
    const int* __restrict__ rows,
    const int* __restrict__ cols,
    const float* __restrict__ vals)
{
    int e = blockIdx.x * blockDim.x + threadIdx.x;
    if (e >= N_EDGES) return;
    int pos = atomicAdd(&g_cur[rows[e]], 1);
    g_edges[pos] = make_int2(cols[e], __float_as_int(vals[e]));
}

// ---------------------------------------------------------------------------
// Fused layer 1: CSR spmm (fp16 gather, MLP8) + bi-interaction 64->64 (FFMA2)
// + l2norm. One warp: 4 rows.
// ---------------------------------------------------------------------------
__global__ __launch_bounds__(256) void k_layer1(
    const float* __restrict__ W1, const float* __restrict__ b1,
    const float* __restrict__ W2, const float* __restrict__ b2,
    float* __restrict__ out)
{
    __shared__ float2 sW[64 * 64];    // [k*64 + j] = (W1[k][j], W2[k][j])
    __shared__ float2 am[8][4][64];   // [warp][row][k] = (ego+side, ego*side)

    int tid = threadIdx.x;
    for (int i = tid; i < 64 * 64; i += 256)
        sW[i] = make_float2(W1[i], W2[i]);
    __syncthreads();

    int warp = tid >> 5;
    int lane = tid & 31;
    int j0 = 2 * lane;
    int rbase = (blockIdx.x * 8 + warp) * 4;

    const float2* egoA2 = (const float2*)g_egoA;

    #pragma unroll
    for (int rr = 0; rr < 4; rr++) {
        int r = rbase + rr;
        if (r >= N_NODES) break;
        int s = g_off[r];
        int e = g_off[r + 1];
        float ax = 0.f, ay = 0.f;
        int i = s;
        for (; i + 7 < e; i += 8) {
            int2 cv[8];
            #pragma unroll
            for (int u = 0; u < 8; u++) cv[u] = g_edges[i + u];
            __half2 hx[8];
            #pragma unroll
            for (int u = 0; u < 8; u++) hx[u] = g_egoAh[cv[u].x * 32 + lane];
            #pragma unroll
            for (int u = 0; u < 8; u++) {
                float2 x = __half22float2(hx[u]);
                float v = __int_as_float(cv[u].y);
                ax = fmaf(v, x.x, ax);
                ay = fmaf(v, x.y, ay);
            }
        }
        for (; i < e; i++) {
            int2 cv = g_edges[i];
            float2 x = __half22float2(g_egoAh[cv.x * 32 + lane]);
            float v = __int_as_float(cv.y);
            ax = fmaf(v, x.x, ax);
            ay = fmaf(v, x.y, ay);
        }
        float2 eg = egoA2[r * 32 + lane];
        am[warp][rr][2 * lane]     = make_float2(eg.x + ax, eg.x * ax);
        am[warp][rr][2 * lane + 1] = make_float2(eg.y + ay, eg.y * ay);
    }
    __syncwarp();

    // acc[rr][c] packed = (sum-path acc, bi-path acc) for output col j0+c
    ull bias0 = pack2(b1[j0], b2[j0]);
    ull bias1 = pack2(b1[j0 + 1], b2[j0 + 1]);
    ull acc[4][2];
    #pragma unroll
    for (int rr = 0; rr < 4; rr++) { acc[rr][0] = bias0; acc[rr][1] = bias1; }

    const ulonglong2* sW2v = (const ulonglong2*)sW;   // [k*32 + lane]
    #pragma unroll 8
    for (int k = 0; k < 64; k++) {
        ulonglong2 w = sW2v[k * 32 + lane];           // (W1,W2)[j0], (W1,W2)[j1]
        #pragma unroll
        for (int rr = 0; rr < 4; rr++) {
            ull amp = *(const ull*)&am[warp][rr][k];  // (a, m)
            fma2(acc[rr][0], amp, w.x);
            fma2(acc[rr][1], amp, w.y);
        }
    }

    #pragma unroll
    for (int rr = 0; rr < 4; rr++) {
        int r = rbase + rr;
        if (r >= N_NODES) break;
        float s0, bb0, s1, bb1v;
        unpack2(acc[rr][0], s0, bb0);
        unpack2(acc[rr][1], s1, bb1v);
        float h0 = (s0 > 0.f ? s0 : 0.01f * s0) + (bb0 > 0.f ? bb0 : 0.01f * bb0);
        float h1 = (s1 > 0.f ? s1 : 0.01f * s1) + (bb1v > 0.f ? bb1v : 0.01f * bb1v);
        float ss = h0 * h0 + h1 * h1;
        #pragma unroll
        for (int off = 16; off > 0; off >>= 1)
            ss += __shfl_xor_sync(0xFFFFFFFFu, ss, off);
        float inv = 1.f / fmaxf(sqrtf(ss), 1e-12f);
        h0 *= inv; h1 *= inv;
        g_egoB[r * 32 + lane] = make_float2(h0, h1);
        g_egoBh[r * 32 + lane] = __floats2half2_rn(h0, h1);
        ((float2*)out)[r * 80 + 32 + lane] = make_float2(h0, h1);
    }
}

// ---------------------------------------------------------------------------
// Fused layer 2: CSR spmm (fp16 gather from ego1) + bi-interaction 64->32 (FFMA2)
// ---------------------------------------------------------------------------
__global__ __launch_bounds__(256) void k_layer2(
    const float* __restrict__ W1, const float* __restrict__ b1,
    const float* __restrict__ W2, const float* __restrict__ b2,
    float* __restrict__ out)
{
    __shared__ float2 sW[64 * 32];    // [k*32 + j] = (W1[k][j], W2[k][j])
    __shared__ float2 am[8][4][64];

    int tid = threadIdx.x;
    for (int i = tid; i < 64 * 32; i += 256)
        sW[i] = make_float2(W1[i], W2[i]);
    __syncthreads();

    int warp = tid >> 5;
    int lane = tid & 31;
    int rbase = (blockIdx.x * 8 + warp) * 4;

    #pragma unroll
    for (int rr = 0; rr < 4; rr++) {
        int r = rbase + rr;
        if (r >= N_NODES) break;
        int s = g_off[r];
        int e = g_off[r + 1];
        float ax = 0.f, ay = 0.f;
        int i = s;
        for (; i + 7 < e; i += 8) {
            int2 cv[8];
            #pragma unroll
            for (int u = 0; u < 8; u++) cv[u] = g_edges[i + u];
            __half2 hx[8];
            #pragma unroll
            for (int u = 0; u < 8; u++) hx[u] = g_egoBh[cv[u].x * 32 + lane];
            #pragma unroll
            for (int u = 0; u < 8; u++) {
                float2 x = __half22float2(hx[u]);
                float v = __int_as_float(cv[u].y);
                ax = fmaf(v, x.x, ax);
                ay = fmaf(v, x.y, ay);
            }
        }
        for (; i < e; i++) {
            int2 cv = g_edges[i];
            float2 x = __half22float2(g_egoBh[cv.x * 32 + lane]);
            float v = __int_as_float(cv.y);
            ax = fmaf(v, x.x, ax);
            ay = fmaf(v, x.y, ay);
        }
        float2 eg = g_egoB[r * 32 + lane];
        am[warp][rr][2 * lane]     = make_float2(eg.x + ax, eg.x * ax);
        am[warp][rr][2 * lane + 1] = make_float2(eg.y + ay, eg.y * ay);
    }
    __syncwarp();

    ull bias = pack2(b1[lane], b2[lane]);
    ull acc[4];
    #pragma unroll
    for (int rr = 0; rr < 4; rr++) acc[rr] = bias;

    const ull* sWv = (const ull*)sW;
    #pragma unroll 8
    for (int k = 0; k < 64; k++) {
        ull w = sWv[k * 32 + lane];
        #pragma unroll
        for (int rr = 0; rr < 4; rr++) {
            ull amp = *(const ull*)&am[warp][rr][k];
            fma2(acc[rr], amp, w);
        }
    }

    #pragma unroll
    for (int rr = 0; rr < 4; rr++) {
        int r = rbase + rr;
        if (r >= N_NODES) break;
        float s, bb;
        unpack2(acc[rr], s, bb);
        float h = (s > 0.f ? s : 0.01f * s) + (bb > 0.f ? bb : 0.01f * bb);
        float ss = h * h;
        #pragma unroll
        for (int off = 16; off > 0; off >>= 1)
            ss += __shfl_xor_sync(0xFFFFFFFFu, ss, off);
        float inv = 1.f / fmaxf(sqrtf(ss), 1e-12f);
        out[r * 160 + 128 + lane] = h * inv;
    }
}

// ---------------------------------------------------------------------------
extern "C" void kernel_launch(void* const* d_in, const int* in_sizes, int n_in,
                              void* d_out, int out_size)
{
    const float* user_tab = (const float*)d_in[0];
    const float* entity_tab = (const float*)d_in[1];
    const float* A_vals = (const float*)d_in[2];
    const float* W1_1 = (const float*)d_in[3];
    const float* b1_1 = (const float*)d_in[4];
    const float* W2_1 = (const float*)d_in[5];
    const float* b2_1 = (const float*)d_in[6];
    const float* W1_2 = (const float*)d_in[7];
    const float* b1_2 = (const float*)d_in[8];
    const float* W2_2 = (const float*)d_in[9];
    const float* b2_2 = (const float*)d_in[10];
    const int* A_rows = (const int*)d_in[11];
    const int* A_cols = (const int*)d_in[12];
    float* out = (float*)d_out;

    int eg = (N_EDGES + 255) / 256;

    void* cnt_ptr = nullptr;
    cudaGetSymbolAddress(&cnt_ptr, g_cnt);
    cudaMemsetAsync(cnt_ptr, 0, N_NODES * sizeof(int));
    void* st_ptr = nullptr;
    cudaGetSymbolAddress(&st_ptr, g_state);
    cudaMemsetAsync(st_ptr, 0, SCAN_NB * sizeof(ull));

    // kernel launch index 0: init (ego + out[:,0:64] + histogram)
    k_init<<<(N_NODES * 16 + 255) / 256, 256>>>(
        (const float4*)user_tab, (const float4*)entity_tab, A_rows, (float4*)out);
    // 1: single-pass scan
    k_scan<<<SCAN_NB, SCAN_BS>>>();
    // 2: scatter into row-sorted edge list
    k_scatter<<<eg, 256>>>(A_rows, A_cols, A_vals);
    // 3: fused layer 1  (profiled by ncu -s5 -c1)
    k_layer1<<<(N_NODES + 31) / 32, 256>>>(W1_1, b1_1, W2_1, b2_1, out);
    // 4: fused layer 2
    k_layer2<<<(N_NODES + 31) / 32, 256>>>(W1_2, b1_2, W2_2, b2_2, out);
}

// round 7
// speedup vs baseline: 1.0970x; 1.0970x over previous
#include <cuda_runtime.h>
#include <cuda_fp16.h>
#include <cstdint>

#define N_USERS 30000
#define N_ENT   70000
#define N_NODES 100000
#define N_EDGES 1600000

#define SCAN_BS 512
#define SCAN_NB ((N_NODES + SCAN_BS - 1) / SCAN_BS)   // 196

typedef unsigned long long ull;

// Scratch
__device__ float4  g_egoA[N_NODES * 16];     // layer-0 ego fp32
__device__ float2  g_egoB[N_NODES * 32];     // layer-1 ego fp32
__device__ __half2 g_egoAh[N_NODES * 32];    // fp16 shadows (gather only)
__device__ __half2 g_egoBh[N_NODES * 32];
__device__ int  g_cnt[N_NODES];
__device__ int  g_off[N_NODES + 1];
__device__ int  g_cur[N_NODES];
__device__ ull  g_state[SCAN_NB];            // lookback: (status<<32)|value
__device__ int2 g_edges[N_EDGES];            // row-sorted (col, val bits)
__device__ float2 g_pack1[64 * 64];          // (W1_1[k][j], W2_1[k][j])
__device__ float2 g_pack2[64 * 32];          // (W1_2[k][j], W2_2[k][j])

// ---- f32x2 packed helpers -------------------------------------------------
__device__ __forceinline__ ull pack2(float a, float b) {
    ull r; asm("mov.b64 %0, {%1, %2};" : "=l"(r) : "f"(a), "f"(b)); return r;
}
__device__ __forceinline__ void unpack2(ull p, float& a, float& b) {
    asm("mov.b64 {%0, %1}, %2;" : "=f"(a), "=f"(b) : "l"(p));
}
__device__ __forceinline__ void fma2(ull& d, ull a, ull b) {
    asm("fma.rn.f32x2 %0, %1, %2, %0;" : "+l"(d) : "l"(a), "l"(b));
}

// ---------------------------------------------------------------------------
// k_init: ego0 (fp32 + fp16 shadow), out[:,0:64], edge histogram, weight pack.
// g_cnt and g_state zeroed beforehand via cudaMemsetAsync.
// ---------------------------------------------------------------------------
__global__ __launch_bounds__(256) void k_init(
    const float4* __restrict__ user4,
    const float4* __restrict__ ent4,
    const int* __restrict__ rows,
    const float* __restrict__ W1_1, const float* __restrict__ W2_1,
    const float* __restrict__ W1_2, const float* __restrict__ W2_2,
    float4* __restrict__ out4)
{
    int idx = blockIdx.x * blockDim.x + threadIdx.x;
    if (idx < N_EDGES) atomicAdd(&g_cnt[rows[idx]], 1);
    if (idx < 64 * 64) g_pack1[idx] = make_float2(W1_1[idx], W2_1[idx]);
    else if (idx < 64 * 64 + 64 * 32) {
        int t = idx - 64 * 64;
        g_pack2[t] = make_float2(W1_2[t], W2_2[t]);
    }
    if (idx >= N_NODES * 16) return;
    int row = idx >> 4;
    int part = idx & 15;
    float4 v = (row < N_USERS) ? user4[row * 16 + part]
                               : ent4[(row - N_USERS) * 16 + part];
    g_egoA[idx] = v;
    g_egoAh[row * 32 + 2 * part]     = __floats2half2_rn(v.x, v.y);
    g_egoAh[row * 32 + 2 * part + 1] = __floats2half2_rn(v.z, v.w);
    out4[row * 40 + part] = v;
}

// ---------------------------------------------------------------------------
// Single-pass exclusive scan of g_cnt (decoupled lookback).
// ---------------------------------------------------------------------------
__global__ __launch_bounds__(SCAN_BS) void k_scan()
{
    __shared__ int warp_sums[16];
    __shared__ int blk_prefix;

    int tid = threadIdx.x;
    int bid = blockIdx.x;
    int lane = tid & 31;
    int wid = tid >> 5;
    int i = bid * SCAN_BS + tid;
    int v = (i < N_NODES) ? g_cnt[i] : 0;

    int x = v;
    #pragma unroll
    for (int off = 1; off < 32; off <<= 1) {
        int t = __shfl_up_sync(0xFFFFFFFFu, x, off);
        if (lane >= off) x += t;
    }
    if (lane == 31) warp_sums[wid] = x;
    __syncthreads();
    if (wid == 0) {
        int s = (lane < 16) ? warp_sums[lane] : 0;
        #pragma unroll
        for (int off = 1; off < 16; off <<= 1) {
            int t = __shfl_up_sync(0xFFFFFFFFu, s, off);
            if (lane >= off) s += t;
        }
        if (lane < 16) warp_sums[lane] = s;
    }
    __syncthreads();
    int incl = x + (wid > 0 ? warp_sums[wid - 1] : 0);
    int block_total = warp_sums[15];

    if (tid == 0) {
        if (bid == 0) {
            atomicExch(&g_state[0], (2ULL << 32) | (unsigned)block_total);
            blk_prefix = 0;
        } else {
            atomicExch(&g_state[bid], (1ULL << 32) | (unsigned)block_total);
            int pref = 0;
            int j = bid - 1;
            while (true) {
                ull s = atomicAdd(&g_state[j], 0ULL);
                unsigned st = (unsigned)(s >> 32);
                if (st == 2) { pref += (int)(unsigned)s; break; }
                if (st == 1) { pref += (int)(unsigned)s; j--; }
            }
            atomicExch(&g_state[bid], (2ULL << 32) | (unsigned)(pref + block_total));
            blk_prefix = pref;
        }
    }
    __syncthreads();

    int excl = blk_prefix + incl - v;
    if (i < N_NODES) { g_off[i] = excl; g_cur[i] = excl; }
    if (i == N_NODES - 1) g_off[N_NODES] = N_EDGES;
}

__global__ __launch_bounds__(256) void k_scatter(
    const int* __restrict__ rows,
    const int* __restrict__ cols,
    const float* __restrict__ vals)
{
    int e = blockIdx.x * blockDim.x + threadIdx.x;
    if (e >= N_EDGES) return;
    int pos = atomicAdd(&g_cur[rows[e]], 1);
    g_edges[pos] = make_int2(cols[e], __float_as_int(vals[e]));
}

// ---------------------------------------------------------------------------
// Gather helper: accumulate side += val * egoH[col] for edges [s, e) of a row.
// Edge descriptors read as int4 (2 edges per load) after parity peel.
// ---------------------------------------------------------------------------
__device__ __forceinline__ void gather_row(
    const __half2* __restrict__ egoH, int lane, int s, int e,
    float& ax, float& ay)
{
    int i = s;
    if ((i & 1) && i < e) {
        int2 cv = g_edges[i];
        float2 x = __half22float2(egoH[cv.x * 32 + lane]);
        float v = __int_as_float(cv.y);
        ax = fmaf(v, x.x, ax); ay = fmaf(v, x.y, ay);
        i++;
    }
    const int4* ep = (const int4*)g_edges;
    for (; i + 7 < e; i += 8) {
        int4 p0 = ep[(i >> 1) + 0];
        int4 p1 = ep[(i >> 1) + 1];
        int4 p2 = ep[(i >> 1) + 2];
        int4 p3 = ep[(i >> 1) + 3];
        __half2 h0 = egoH[p0.x * 32 + lane];
        __half2 h1 = egoH[p0.z * 32 + lane];
        __half2 h2 = egoH[p1.x * 32 + lane];
        __half2 h3 = egoH[p1.z * 32 + lane];
        __half2 h4 = egoH[p2.x * 32 + lane];
        __half2 h5 = egoH[p2.z * 32 + lane];
        __half2 h6 = egoH[p3.x * 32 + lane];
        __half2 h7 = egoH[p3.z * 32 + lane];
        float2 x;
        x = __half22float2(h0); ax = fmaf(__int_as_float(p0.y), x.x, ax); ay = fmaf(__int_as_float(p0.y), x.y, ay);
        x = __half22float2(h1); ax = fmaf(__int_as_float(p0.w), x.x, ax); ay = fmaf(__int_as_float(p0.w), x.y, ay);
        x = __half22float2(h2); ax = fmaf(__int_as_float(p1.y), x.x, ax); ay = fmaf(__int_as_float(p1.y), x.y, ay);
        x = __half22float2(h3); ax = fmaf(__int_as_float(p1.w), x.x, ax); ay = fmaf(__int_as_float(p1.w), x.y, ay);
        x = __half22float2(h4); ax = fmaf(__int_as_float(p2.y), x.x, ax); ay = fmaf(__int_as_float(p2.y), x.y, ay);
        x = __half22float2(h5); ax = fmaf(__int_as_float(p2.w), x.x, ax); ay = fmaf(__int_as_float(p2.w), x.y, ay);
        x = __half22float2(h6); ax = fmaf(__int_as_float(p3.y), x.x, ax); ay = fmaf(__int_as_float(p3.y), x.y, ay);
        x = __half22float2(h7); ax = fmaf(__int_as_float(p3.w), x.x, ax); ay = fmaf(__int_as_float(p3.w), x.y, ay);
    }
    for (; i < e; i++) {
        int2 cv = g_edges[i];
        float2 x = __half22float2(egoH[cv.x * 32 + lane]);
        float v = __int_as_float(cv.y);
        ax = fmaf(v, x.x, ax); ay = fmaf(v, x.y, ay);
    }
}

// ---------------------------------------------------------------------------
// Fused layer 1: CSR spmm (fp16 gather) + bi-interaction 64->64 (FFMA2,
// weights via L1-resident __ldg) + l2norm. One warp: 4 rows. No block sync.
// ---------------------------------------------------------------------------
__global__ __launch_bounds__(256, 5) void k_layer1(
    const float* __restrict__ b1, const float* __restrict__ b2,
    float* __restrict__ out)
{
    __shared__ float2 am[8][4][64];   // [warp][row][k] = (ego+side, ego*side)

    int tid = threadIdx.x;
    int warp = tid >> 5;
    int lane = tid & 31;
    int j0 = 2 * lane;
    int rbase = (blockIdx.x * 8 + warp) * 4;

    const float2* egoA2 = (const float2*)g_egoA;

    #pragma unroll
    for (int rr = 0; rr < 4; rr++) {
        int r = rbase + rr;
        if (r >= N_NODES) break;
        float ax = 0.f, ay = 0.f;
        gather_row(g_egoAh, lane, g_off[r], g_off[r + 1], ax, ay);
        float2 eg = egoA2[r * 32 + lane];
        am[warp][rr][2 * lane]     = make_float2(eg.x + ax, eg.x * ax);
        am[warp][rr][2 * lane + 1] = make_float2(eg.y + ay, eg.y * ay);
    }
    __syncwarp();

    ull bias0 = pack2(b1[j0], b2[j0]);
    ull bias1 = pack2(b1[j0 + 1], b2[j0 + 1]);
    ull acc[4][2];
    #pragma unroll
    for (int rr = 0; rr < 4; rr++) { acc[rr][0] = bias0; acc[rr][1] = bias1; }

    const float4* Wp = (const float4*)g_pack1;   // [k*32+lane] = (W1,W2)[j0],(W1,W2)[j1]
    #pragma unroll 8
    for (int k = 0; k < 64; k++) {
        float4 w = __ldg(&Wp[k * 32 + lane]);
        ull wx = pack2(w.x, w.y);
        ull wy = pack2(w.z, w.w);
        #pragma unroll
        for (int rr = 0; rr < 4; rr++) {
            ull amp = *(const ull*)&am[warp][rr][k];
            fma2(acc[rr][0], amp, wx);
            fma2(acc[rr][1], amp, wy);
        }
    }

    #pragma unroll
    for (int rr = 0; rr < 4; rr++) {
        int r = rbase + rr;
        if (r >= N_NODES) break;
        float s0, bb0, s1, bb1v;
        unpack2(acc[rr][0], s0, bb0);
        unpack2(acc[rr][1], s1, bb1v);
        float h0 = (s0 > 0.f ? s0 : 0.01f * s0) + (bb0 > 0.f ? bb0 : 0.01f * bb0);
        float h1 = (s1 > 0.f ? s1 : 0.01f * s1) + (bb1v > 0.f ? bb1v : 0.01f * bb1v);
        float ss = h0 * h0 + h1 * h1;
        #pragma unroll
        for (int off = 16; off > 0; off >>= 1)
            ss += __shfl_xor_sync(0xFFFFFFFFu, ss, off);
        float inv = 1.f / fmaxf(sqrtf(ss), 1e-12f);
        h0 *= inv; h1 *= inv;
        g_egoB[r * 32 + lane] = make_float2(h0, h1);
        g_egoBh[r * 32 + lane] = __floats2half2_rn(h0, h1);
        ((float2*)out)[r * 80 + 32 + lane] = make_float2(h0, h1);
    }
}

// ---------------------------------------------------------------------------
// Fused layer 2: CSR spmm (fp16 gather from ego1) + bi-interaction 64->32.
// ---------------------------------------------------------------------------
__global__ __launch_bounds__(256, 5) void k_layer2(
    const float* __restrict__ b1, const float* __restrict__ b2,
    float* __restrict__ out)
{
    __shared__ float2 am[8][4][64];

    int tid = threadIdx.x;
    int warp = tid >> 5;
    int lane = tid & 31;
    int rbase = (blockIdx.x * 8 + warp) * 4;

    #pragma unroll
    for (int rr = 0; rr < 4; rr++) {
        int r = rbase + rr;
        if (r >= N_NODES) break;
        float ax = 0.f, ay = 0.f;
        gather_row(g_egoBh, lane, g_off[r], g_off[r + 1], ax, ay);
        float2 eg = g_egoB[r * 32 + lane];
        am[warp][rr][2 * lane]     = make_float2(eg.x + ax, eg.x * ax);
        am[warp][rr][2 * lane + 1] = make_float2(eg.y + ay, eg.y * ay);
    }
    __syncwarp();

    ull bias = pack2(b1[lane], b2[lane]);
    ull acc[4];
    #pragma unroll
    for (int rr = 0; rr < 4; rr++) acc[rr] = bias;

    #pragma unroll 8
    for (int k = 0; k < 64; k++) {
        float2 w = __ldg(&g_pack2[k * 32 + lane]);
        ull wp = pack2(w.x, w.y);
        #pragma unroll
        for (int rr = 0; rr < 4; rr++) {
            ull amp = *(const ull*)&am[warp][rr][k];
            fma2(acc[rr], amp, wp);
        }
    }

    #pragma unroll
    for (int rr = 0; rr < 4; rr++) {
        int r = rbase + rr;
        if (r >= N_NODES) break;
        float s, bb;
        unpack2(acc[rr], s, bb);
        float h = (s > 0.f ? s : 0.01f * s) + (bb > 0.f ? bb : 0.01f * bb);
        float ss = h * h;
        #pragma unroll
        for (int off = 16; off > 0; off >>= 1)
            ss += __shfl_xor_sync(0xFFFFFFFFu, ss, off);
        float inv = 1.f / fmaxf(sqrtf(ss), 1e-12f);
        out[r * 160 + 128 + lane] = h * inv;
    }
}

// ---------------------------------------------------------------------------
extern "C" void kernel_launch(void* const* d_in, const int* in_sizes, int n_in,
                              void* d_out, int out_size)
{
    const float* user_tab = (const float*)d_in[0];
    const float* entity_tab = (const float*)d_in[1];
    const float* A_vals = (const float*)d_in[2];
    const float* W1_1 = (const float*)d_in[3];
    const float* b1_1 = (const float*)d_in[4];
    const float* W2_1 = (const float*)d_in[5];
    const float* b2_1 = (const float*)d_in[6];
    const float* W1_2 = (const float*)d_in[7];
    const float* b1_2 = (const float*)d_in[8];
    const float* W2_2 = (const float*)d_in[9];
    const float* b2_2 = (const float*)d_in[10];
    const int* A_rows = (const int*)d_in[11];
    const int* A_cols = (const int*)d_in[12];
    float* out = (float*)d_out;

    int eg = (N_EDGES + 255) / 256;

    void* cnt_ptr = nullptr;
    cudaGetSymbolAddress(&cnt_ptr, g_cnt);
    cudaMemsetAsync(cnt_ptr, 0, N_NODES * sizeof(int));
    void* st_ptr = nullptr;
    cudaGetSymbolAddress(&st_ptr, g_state);
    cudaMemsetAsync(st_ptr, 0, SCAN_NB * sizeof(ull));

    // 0: init (ego + out[:,0:64] + histogram + weight pack)
    k_init<<<(N_NODES * 16 + 255) / 256, 256>>>(
        (const float4*)user_tab, (const float4*)entity_tab, A_rows,
        W1_1, W2_1, W1_2, W2_2, (float4*)out);
    // 1: single-pass scan
    k_scan<<<SCAN_NB, SCAN_BS>>>();
    // 2: scatter into row-sorted edge list
    k_scatter<<<eg, 256>>>(A_rows, A_cols, A_vals);
    // 3: fused layer 1  (profiled by ncu -s5 -c1)
    k_layer1<<<(N_NODES + 31) / 32, 256>>>(b1_1, b2_1, out);
    // 4: fused layer 2
    k_layer2<<<(N_NODES + 31) / 32, 256>>>(b1_2, b2_2, out);
}